// round 2
// baseline (speedup 1.0000x reference)
#include <cuda_runtime.h>

#define ETA 1e-5f

static const int D    = 1024;
static const int DA   = 1023;   // a = x[:-1]
static const int M2   = 512;
static const int NMAX = 20000;

// Static device scratch (no runtime allocation allowed)
__device__ float g_AtT[(size_t)NMAX * D];   // transposed At: row i = x_i (contiguous)
__device__ float g_Tsq[(size_t)NMAX * M2];  // per-step per-row t_r^2 partials
__device__ float g_T2[NMAX];                // per-step ||t||^2

// ---------------------------------------------------------------------------
// Kernel 0: transpose At (D x N) -> g_AtT (N x D)
// ---------------------------------------------------------------------------
__global__ void k_transpose(const float* __restrict__ At, int N) {
    __shared__ float tile[32][33];
    int i0 = blockIdx.x * 32;           // N dim
    int r0 = blockIdx.y * 32;           // D dim
    int tx = threadIdx.x, ty = threadIdx.y;   // blockDim (32, 8)
    #pragma unroll
    for (int k = 0; k < 32; k += 8) {
        int r = r0 + ty + k, i = i0 + tx;
        if (i < N) tile[ty + k][tx] = At[(size_t)r * N + i];
    }
    __syncthreads();
    #pragma unroll
    for (int k = 0; k < 32; k += 8) {
        int i = i0 + ty + k, r = r0 + tx;
        if (i < N) g_AtT[(size_t)i * D + r] = tile[tx][ty + k];
    }
}

// ---------------------------------------------------------------------------
// Shared helpers
// ---------------------------------------------------------------------------
__device__ __forceinline__ void ldx(float (&x)[32], int i, int c0, bool mask_last) {
    const float4* p = reinterpret_cast<const float4*>(&g_AtT[(size_t)i * D + c0]);
    #pragma unroll
    for (int j = 0; j < 8; j++) {
        float4 v = p[j];
        x[4*j+0] = v.x; x[4*j+1] = v.y; x[4*j+2] = v.z; x[4*j+3] = v.w;
    }
    if (mask_last && c0 == 31 * 32) x[31] = 0.f;   // a[1023] doesn't exist
}

__device__ __forceinline__ float warp_sum(float s) {
    #pragma unroll
    for (int o = 16; o; o >>= 1) s += __shfl_xor_sync(0xffffffffu, s, o);
    return s;
}

// ---------------------------------------------------------------------------
// Kernel 1: W2 path. 512 warps, warp r owns g_W2 row r in registers.
// ---------------------------------------------------------------------------
__device__ __forceinline__ void w2_step(float (&G)[32], const float (&x)[32], int i, int r) {
    float a0 = 0.f, a1 = 0.f, a2 = 0.f, a3 = 0.f;
    #pragma unroll
    for (int k = 0; k < 32; k += 4) {
        a0 = fmaf(G[k+0], x[k+0], a0);
        a1 = fmaf(G[k+1], x[k+1], a1);
        a2 = fmaf(G[k+2], x[k+2], a2);
        a3 = fmaf(G[k+3], x[k+3], a3);
    }
    float t  = -ETA * warp_sum((a0 + a1) + (a2 + a3));   // t_r = (-ETA * g_W2)[r] . a
    float t2 = 2.f * t;
    #pragma unroll
    for (int k = 0; k < 32; k++) G[k] = fmaf(t2, x[k], G[k]);   // g_W2 += 2 t a^T
    if ((threadIdx.x & 31) == 0) g_Tsq[(size_t)i * M2 + r] = t * t;
}

__global__ void __launch_bounds__(128) k_w2(const float* __restrict__ W2init, int N) {
    int r    = (blockIdx.x * 128 + threadIdx.x) >> 5;   // 0..511
    int lane = threadIdx.x & 31;
    int c0   = lane * 32;

    float G[32];
    float xa[32], xb[32];

    // ---- step 0: t0 = W2_init[r] . a0 ; g_W2 = 2 t0 a0^T
    ldx(xa, 0, c0, true);
    {
        const float* wrow = W2init + (size_t)r * DA;
        float a0 = 0.f, a1 = 0.f, a2 = 0.f, a3 = 0.f;
        #pragma unroll
        for (int k = 0; k < 32; k += 4) {
            float w0 = (c0+k+0 < DA) ? __ldg(wrow + c0+k+0) : 0.f;
            float w1 = (c0+k+1 < DA) ? __ldg(wrow + c0+k+1) : 0.f;
            float w2 = (c0+k+2 < DA) ? __ldg(wrow + c0+k+2) : 0.f;
            float w3 = (c0+k+3 < DA) ? __ldg(wrow + c0+k+3) : 0.f;
            a0 = fmaf(w0, xa[k+0], a0);
            a1 = fmaf(w1, xa[k+1], a1);
            a2 = fmaf(w2, xa[k+2], a2);
            a3 = fmaf(w3, xa[k+3], a3);
        }
        float t  = warp_sum((a0 + a1) + (a2 + a3));   // step 0 uses W2_init directly
        float t2 = 2.f * t;
        #pragma unroll
        for (int k = 0; k < 32; k++) G[k] = t2 * xa[k];
        if (lane == 0) g_Tsq[r] = t * t;
    }

    // ---- steps 1..N-1, double-buffered x, 2x unrolled so buffers swap roles
    ldx(xb, 1, c0, true);
    for (int i = 1; i < N; i += 2) {
        if (i + 1 < N) ldx(xa, i + 1, c0, true);
        w2_step(G, xb, i, r);
        if (i + 1 < N) {
            if (i + 2 < N) ldx(xb, i + 2, c0, true);
            w2_step(G, xa, i + 1, r);
        }
    }
}

// ---------------------------------------------------------------------------
// Kernel 1b: T2[i] = sum_r Tsq[i, r]   (one warp per step)
// ---------------------------------------------------------------------------
__global__ void k_reduce(int N) {
    int w    = (blockIdx.x * blockDim.x + threadIdx.x) >> 5;
    int lane = threadIdx.x & 31;
    if (w >= N) return;
    const float* p = g_Tsq + (size_t)w * M2;
    float s = 0.f;
    #pragma unroll
    for (int j = 0; j < 16; j++) s += p[lane + 32 * j];
    s = warp_sum(s);
    if (lane == 0) g_T2[w] = s;
}

// ---------------------------------------------------------------------------
// Kernel 2: w1 scalar scan. One warp; g_w1 in registers (32 floats/lane).
// ---------------------------------------------------------------------------
__device__ __forceinline__ void w1_step(float (&g)[32], const float (&x)[32], int i,
                                        float bi, float t2i, float* __restrict__ preds) {
    float a0 = 0.f, a1 = 0.f, a2 = 0.f, a3 = 0.f;
    #pragma unroll
    for (int k = 0; k < 32; k += 4) {
        a0 = fmaf(g[k+0], x[k+0], a0);
        a1 = fmaf(g[k+1], x[k+1], a1);
        a2 = fmaf(g[k+2], x[k+2], a2);
        a3 = fmaf(g[k+3], x[k+3], a3);
    }
    float s      = warp_sum((a0 + a1) + (a2 + a3));
    float scalar = -ETA * s + t2i;                 // w1 = -ETA * g_w1
    if (threadIdx.x == 0) preds[i] = scalar;
    float sign = 2.f * (scalar - bi);
    #pragma unroll
    for (int k = 0; k < 32; k++) g[k] = fmaf(sign, x[k], g[k]);   // g_w1 += sign x
}

__global__ void k_w1(const float* __restrict__ w1init, const float* __restrict__ b,
                     float* __restrict__ preds, int N) {
    int lane = threadIdx.x;
    int c0   = lane * 32;
    float g[32];
    float xa[32], xb[32];

    // ---- step 0 with w1_init
    ldx(xa, 0, c0, false);
    {
        float a0 = 0.f, a1 = 0.f, a2 = 0.f, a3 = 0.f;
        #pragma unroll
        for (int k = 0; k < 32; k += 4) {
            a0 = fmaf(__ldg(w1init + c0+k+0), xa[k+0], a0);
            a1 = fmaf(__ldg(w1init + c0+k+1), xa[k+1], a1);
            a2 = fmaf(__ldg(w1init + c0+k+2), xa[k+2], a2);
            a3 = fmaf(__ldg(w1init + c0+k+3), xa[k+3], a3);
        }
        float s      = warp_sum((a0 + a1) + (a2 + a3));
        float scalar = s + g_T2[0];
        if (lane == 0) preds[0] = scalar;
        float sign = 2.f * (scalar - __ldg(b));
        #pragma unroll
        for (int k = 0; k < 32; k++) g[k] = sign * xa[k];   // g_w1 started at 0
    }

    // ---- steps 1..N-1, double-buffered x + prefetched b/T2 scalars
    ldx(xb, 1, c0, false);
    float bb = __ldg(b + 1), tb = g_T2[1];
    for (int i = 1; i < N; i += 2) {
        float ba = 0.f, ta = 0.f;
        if (i + 1 < N) { ldx(xa, i + 1, c0, false); ba = __ldg(b + i + 1); ta = g_T2[i + 1]; }
        w1_step(g, xb, i, bb, tb, preds);
        if (i + 1 < N) {
            if (i + 2 < N) { ldx(xb, i + 2, c0, false); bb = __ldg(b + i + 2); tb = g_T2[i + 2]; }
            w1_step(g, xa, i + 1, ba, ta, preds);
        }
    }
}

// ---------------------------------------------------------------------------
// Kernel 3: copy b into second half of output
// ---------------------------------------------------------------------------
__global__ void k_copyb(const float* __restrict__ b, float* __restrict__ out, int N) {
    int i = blockIdx.x * blockDim.x + threadIdx.x;
    if (i < N) out[i] = b[i];
}

// ---------------------------------------------------------------------------
extern "C" void kernel_launch(void* const* d_in, const int* in_sizes, int n_in,
                              void* d_out, int out_size) {
    const float* At = (const float*)d_in[0];
    const float* b  = (const float*)d_in[1];
    const float* w1 = (const float*)d_in[2];
    const float* W2 = (const float*)d_in[3];
    int N = in_sizes[1];                 // 20000
    float* out = (float*)d_out;

    dim3 tb(32, 8);
    dim3 tg((N + 31) / 32, D / 32);
    k_transpose<<<tg, tb>>>(At, N);

    k_w2<<<128, 128>>>(W2, N);           // 512 warps = 512 rows

    int warps_needed = N;
    k_reduce<<<(warps_needed * 32 + 255) / 256, 256>>>(N);

    k_w1<<<1, 32>>>(w1, b, out, N);

    if (out_size >= 2 * N)
        k_copyb<<<(N + 255) / 256, 256>>>(b, out + N, N);
}